// round 5
// baseline (speedup 1.0000x reference)
#include <cuda_runtime.h>
#include <math.h>

typedef unsigned long long u64;

// Problem constants
#define BB 256
#define TT 512
#define HH 128
#define VV 29275
#define G3 384          // 3*H
#define GM 16           // gemm row tile
#define NCTA 148        // persistent gemm grid

// Scratch (static device globals — no runtime allocation)
__device__ float g_G0[VV * G3];        // emb @ Wih0^T + b_ih0   (~45 MB)
__device__ float g_h0[BB * TT * HH];   // layer-0 hidden outputs (~64 MB)
__device__ float g_gx1[BB * TT * G3];  // h0 @ Wih1^T + b_ih1    (~201 MB)
__device__ float g_hlast[BB * HH];     // layer-1 final hidden

// ---------------------------------------------------------------------------
// f32x2 packed helpers
// ---------------------------------------------------------------------------
__device__ __forceinline__ u64 ffma2(u64 a, u64 b, u64 c) {
    u64 d;
    asm("fma.rn.f32x2 %0, %1, %2, %3;" : "=l"(d) : "l"(a), "l"(b), "l"(c));
    return d;
}
__device__ __forceinline__ float2 unpk(u64 v) {
    float2 r;
    asm("mov.b64 {%0, %1}, %2;" : "=f"(r.x), "=f"(r.y) : "l"(v));
    return r;
}

// single-MUFU activations
__device__ __forceinline__ float mtanh(float v) {
    float r;
    asm("tanh.approx.f32 %0, %1;" : "=f"(r) : "f"(v));
    return r;
}
__device__ __forceinline__ float msig(float v) {
    return fmaf(0.5f, mtanh(0.5f * v), 0.5f);
}

// ---------------------------------------------------------------------------
// Persistent GEMM: OUT[m, j] = bias[j] + sum_k A[m,k] * W[j,k]
// (unchanged from R3 — near crossbar/fma balance)
// ---------------------------------------------------------------------------
__global__ void __launch_bounds__(G3, 1)
gemm_persist(const float* __restrict__ A_ext, const float* __restrict__ W,
             const float* __restrict__ bias, int M, int mode)
{
    extern __shared__ char smraw[];
    ulonglong2* __restrict__ Wsm = (ulonglong2*)smraw;            // 48 KB
    float*      __restrict__ As  = (float*)(smraw + 8 * G3 * 16); // 16 KB

    const float* __restrict__ A = mode ? g_h0 : A_ext;
    float* __restrict__ OUT     = mode ? g_gx1 : g_G0;

    const int j = threadIdx.x;

    for (int idx = j; idx < G3 * 8; idx += G3) {
        int jj = idx >> 3, q = idx & 7;
        Wsm[q * G3 + jj] = ((const ulonglong2*)(W + jj * HH + 96))[q];
    }
    u64 wreg[48];
    {
        const ulonglong2* __restrict__ Wr = (const ulonglong2*)(W + j * HH);
#pragma unroll
        for (int q = 0; q < 24; q++) {
            ulonglong2 w = Wr[q];
            wreg[2 * q] = w.x; wreg[2 * q + 1] = w.y;
        }
    }
    const float bj = bias[j];

    const int ntiles = (M + GM - 1) / GM;
    int it = blockIdx.x;
    if (it >= ntiles) return;

    float4 r0 = make_float4(0, 0, 0, 0), r1 = make_float4(0, 0, 0, 0);
    {
        int m = j >> 5, c = j & 31, mm = it * GM + m;
        if (mm < M) r0 = ((const float4*)(A + mm * HH))[c];
        if (j < 128) {
            int m2 = (j + G3) >> 5, c2 = (j + G3) & 31, mm2 = it * GM + m2;
            if (mm2 < M) r1 = ((const float4*)(A + mm2 * HH))[c2];
        }
    }
    ((float4*)As)[j] = r0;
    if (j < 128) ((float4*)As)[j + G3] = r1;
    __syncthreads();

    int buf = 0;
    for (; it < ntiles; it += NCTA, buf ^= 1) {
        const int nxt = it + NCTA;
        if (nxt < ntiles) {
            r0 = make_float4(0, 0, 0, 0); r1 = make_float4(0, 0, 0, 0);
            int m = j >> 5, c = j & 31, mm = nxt * GM + m;
            if (mm < M) r0 = ((const float4*)(A + mm * HH))[c];
            if (j < 128) {
                int m2 = (j + G3) >> 5, c2 = (j + G3) & 31, mm2 = nxt * GM + m2;
                if (mm2 < M) r1 = ((const float4*)(A + mm2 * HH))[c2];
            }
        }

        u64 acc[GM];
#pragma unroll
        for (int m = 0; m < GM; m++) acc[m] = 0ull;
        const ulonglong2* __restrict__ At = (const ulonglong2*)(As + (buf ? GM * HH : 0));
#pragma unroll
        for (int q = 0; q < 24; q++) {
            u64 wx = wreg[2 * q], wy = wreg[2 * q + 1];
#pragma unroll
            for (int m = 0; m < GM; m++) {
                ulonglong2 a = At[m * 32 + q];
                acc[m] = ffma2(wx, a.x, acc[m]);
                acc[m] = ffma2(wy, a.y, acc[m]);
            }
        }
#pragma unroll
        for (int q = 0; q < 8; q++) {
            ulonglong2 w = Wsm[q * G3 + j];
#pragma unroll
            for (int m = 0; m < GM; m++) {
                ulonglong2 a = At[m * 32 + 24 + q];
                acc[m] = ffma2(w.x, a.x, acc[m]);
                acc[m] = ffma2(w.y, a.y, acc[m]);
            }
        }

        const int m0 = it * GM;
#pragma unroll
        for (int m = 0; m < GM; m++) {
            if (m0 + m < M) {
                float2 s = unpk(acc[m]);
                OUT[(m0 + m) * G3 + j] = bj + s.x + s.y;
            }
        }

        if (nxt < ntiles) {
            float* Ad = As + (buf ? 0 : GM * HH);
            ((float4*)Ad)[j] = r0;
            if (j < 128) ((float4*)Ad)[j + G3] = r1;
        }
        __syncthreads();
    }
}

// ---------------------------------------------------------------------------
// Persistent GRU scan, k-split edition.
// 128 CTAs x 768 threads (24 warps). Thread (j, kh): j = w*16 + (lane&15),
// kh = lane>>4 selects k-half. Each thread: 64-float k-half dot for both
// batch rows; halves combined via shfl.xor(16). W: 56 floats in regs,
// 8 floats in SMEM. h loads use interleaved entries (e = 2i + kh) so each
// warp LDS.128 touches 32B contiguous -> 1 wavefront.
// Warps 0-7: r gates; 8-15: z; 16-23: n + state update (row kh each).
// ---------------------------------------------------------------------------
__global__ void __launch_bounds__(768, 1)
gru_scan(const float* __restrict__ Whh, const float* __restrict__ bhh,
         const int* __restrict__ x, int layer)
{
    extern __shared__ ulonglong2 Wsm[];             // [2][768]  24 KB
    __shared__ __align__(16) float hbuf[2][2][HH];  // [buf][row][k]
    __shared__ float2 rp[HH], zp[HH];
    __shared__ int    xs[2][TT];

    const int tid = threadIdx.x;
    const int l   = tid & 31;
    const int j   = ((tid >> 5) << 4) | (l & 15);   // gate row 0..383
    const int kh  = l >> 4;                         // k-half 0/1
    const int b0  = blockIdx.x * 2, b1 = b0 + 1;
    const float* __restrict__ gxT = layer ? g_gx1 : g_G0;

    // --- init: W (56 floats reg, 8 smem), tokens, h=0 ---
    u64 wreg[28];
    {
        const ulonglong2* __restrict__ Wr = (const ulonglong2*)(Whh + j * HH);
#pragma unroll
        for (int i = 0; i < 14; i++) {              // entries e = 2i+kh
            ulonglong2 v = Wr[2 * i + kh];
            wreg[2 * i]     = v.x;
            wreg[2 * i + 1] = v.y;
        }
        Wsm[tid]       = Wr[28 + kh];               // i = 14
        Wsm[768 + tid] = Wr[30 + kh];               // i = 15
    }
    for (int i = tid; i < 2 * TT; i += 768) {
        int r = i >> 9, t = i & (TT - 1);
        ((int*)xs)[i] = x[(b0 + r) * TT + t];
    }
    if (tid < HH) { hbuf[0][0][tid] = 0.0f; hbuf[0][1][tid] = 0.0f; }
    const float bh = bhh[j];
    __syncthreads();

    // preload gx for t=0 (both rows)
    float gxa, gxb;
    if (layer == 0) {
        gxa = __ldg(&gxT[xs[0][0] * G3 + j]);
        gxb = __ldg(&gxT[xs[1][0] * G3 + j]);
    } else {
        gxa = __ldg(&gxT[(b0 * TT) * G3 + j]);
        gxb = __ldg(&gxT[(b1 * TT) * G3 + j]);
    }

    for (int t = 0; t < TT; t++) {
        const int buf = t & 1;

        // prefetch next step's input gates
        float ngxa = 0.0f, ngxb = 0.0f;
        if (t + 1 < TT) {
            if (layer == 0) {
                ngxa = __ldg(&gxT[xs[0][t + 1] * G3 + j]);
                ngxb = __ldg(&gxT[xs[1][t + 1] * G3 + j]);
            } else {
                ngxa = __ldg(&gxT[(b0 * TT + t + 1) * G3 + j]);
                ngxb = __ldg(&gxT[(b1 * TT + t + 1) * G3 + j]);
            }
        }

        // partial dot over this thread's k-half, both rows
        const ulonglong2* __restrict__ h0p = (const ulonglong2*)hbuf[buf][0] + kh;
        const ulonglong2* __restrict__ h1p = (const ulonglong2*)hbuf[buf][1] + kh;
        u64 a0 = 0ull, a0b = 0ull, a1 = 0ull, a1b = 0ull;
#pragma unroll
        for (int i = 0; i < 14; i++) {
            ulonglong2 ha = h0p[2 * i];
            ulonglong2 hb = h1p[2 * i];
            a0  = ffma2(wreg[2 * i],     ha.x, a0);
            a0b = ffma2(wreg[2 * i + 1], ha.y, a0b);
            a1  = ffma2(wreg[2 * i],     hb.x, a1);
            a1b = ffma2(wreg[2 * i + 1], hb.y, a1b);
        }
#pragma unroll
        for (int s = 0; s < 2; s++) {
            ulonglong2 wv = Wsm[s * 768 + tid];
            ulonglong2 ha = h0p[28 + 2 * s];
            ulonglong2 hb = h1p[28 + 2 * s];
            a0  = ffma2(wv.x, ha.x, a0);
            a0b = ffma2(wv.y, ha.y, a0b);
            a1  = ffma2(wv.x, hb.x, a1);
            a1b = ffma2(wv.y, hb.y, a1b);
        }
        float2 f0 = unpk(a0), f0b = unpk(a0b), f1 = unpk(a1), f1b = unpk(a1b);
        float p0 = (f0.x + f0.y) + (f0b.x + f0b.y);
        float p1 = (f1.x + f1.y) + (f1b.x + f1b.y);
        p0 += __shfl_xor_sync(0xffffffffu, p0, 16);
        p1 += __shfl_xor_sync(0xffffffffu, p1, 16);
        const float gh0 = bh + p0;
        const float gh1 = bh + p1;

        if (j < 2 * HH) {
            // producers: r (warps 0-7) / z (warps 8-15)
            if (kh == 0) {
                float2 v = make_float2(msig(gxa + gh0), msig(gxb + gh1));
                if (j < HH) rp[j] = v; else zp[j - HH] = v;
            }
            asm volatile("bar.arrive 1, 768;" ::: "memory");
        } else {
            // consumers: n gate + state update; thread handles row kh only
            const int i = j - 2 * HH;
            const float hold = hbuf[buf][kh][i];
            asm volatile("bar.sync 1, 768;" ::: "memory");
            float2 rv = rp[i], zv = zp[i];
            const float gxn = kh ? gxb : gxa;
            const float ghn = kh ? gh1 : gh0;
            const float r   = kh ? rv.y : rv.x;
            const float z   = kh ? zv.y : zv.x;
            float n  = mtanh(gxn + r * ghn);
            float hn = n + z * (hold - n);          // (1-z)*n + z*h
            hbuf[buf ^ 1][kh][i] = hn;
            if (layer == 0) {
                g_h0[((kh ? b1 : b0) * TT + t) * HH + i] = hn;
            } else if (t == TT - 1) {
                g_hlast[(kh ? b1 : b0) * HH + i] = hn;
            }
        }
        __syncthreads();
        gxa = ngxa;
        gxb = ngxb;
    }
}

// ---------------------------------------------------------------------------
__global__ void __launch_bounds__(BB)
fc_kernel(const float* __restrict__ fcw, const float* __restrict__ fcb,
          float* __restrict__ out)
{
    __shared__ float ws[3 * HH];
    int b = threadIdx.x;
    for (int i = b; i < 3 * HH; i += BB) ws[i] = fcw[i];
    __syncthreads();
    float a0 = fcb[0], a1 = fcb[1], a2 = fcb[2];
#pragma unroll 4
    for (int k = 0; k < HH; k++) {
        float h = g_hlast[b * HH + k];
        h = h > 0.0f ? h : 0.0f;
        a0 = fmaf(h, ws[k], a0);
        a1 = fmaf(h, ws[HH + k], a1);
        a2 = fmaf(h, ws[2 * HH + k], a2);
    }
    out[b * 3 + 0] = a0;
    out[b * 3 + 1] = a1;
    out[b * 3 + 2] = a2;
}

// ---------------------------------------------------------------------------
extern "C" void kernel_launch(void* const* d_in, const int* in_sizes, int n_in,
                              void* d_out, int out_size)
{
    const int*   x    = (const int*)  d_in[0];
    const float* emb  = (const float*)d_in[1];
    const float* W_ih = (const float*)d_in[2];   // [2][384][128]
    const float* W_hh = (const float*)d_in[3];   // [2][384][128]
    const float* b_ih = (const float*)d_in[4];   // [2][384]
    const float* b_hh = (const float*)d_in[5];   // [2][384]
    const float* fc_w = (const float*)d_in[6];   // [3][128]
    const float* fc_b = (const float*)d_in[7];   // [3]
    float* out = (float*)d_out;

    const int smem_scan = 2 * 768 * (int)sizeof(ulonglong2);            // 24 KB
    const int smem_gemm = 8 * G3 * 16 + 2 * GM * HH * (int)sizeof(float); // 64 KB
    cudaFuncSetAttribute(gru_scan, cudaFuncAttributeMaxDynamicSharedMemorySize,
                         smem_scan);
    cudaFuncSetAttribute(gemm_persist, cudaFuncAttributeMaxDynamicSharedMemorySize,
                         smem_gemm);

    // 1) G0 = emb @ Wih0^T + b_ih0  (vocab-side precompute: V < B*T)
    gemm_persist<<<NCTA, G3, smem_gemm>>>(emb, W_ih, b_ih, VV, 0);
    // 2) layer-0 scan (gx gathered from G0), writes g_h0
    gru_scan<<<BB / 2, 768, smem_scan>>>(W_hh, b_hh, x, 0);
    // 3) gx1 = h0 @ Wih1^T + b_ih1
    gemm_persist<<<NCTA, G3, smem_gemm>>>(nullptr, W_ih + G3 * HH, b_ih + G3, BB * TT, 1);
    // 4) layer-1 scan, writes g_hlast
    gru_scan<<<BB / 2, 768, smem_scan>>>(W_hh + G3 * HH, b_hh + G3, x, 1);
    // 5) head
    fc_kernel<<<1, BB>>>(fc_w, fc_b, out);
}

// round 6
// speedup vs baseline: 1.4905x; 1.4905x over previous
#include <cuda_runtime.h>
#include <math.h>

typedef unsigned long long u64;

// Problem constants
#define BB 256
#define TT 512
#define HH 128
#define VV 29275
#define G3 384          // 3*H
#define GM 16           // gemm row tile
#define NCTA 148        // persistent gemm grid

// Scratch (static device globals — no runtime allocation)
__device__ float g_G0[VV * G3];        // emb @ Wih0^T + b_ih0   (~45 MB)
__device__ float g_h0[BB * TT * HH];   // layer-0 hidden outputs (~64 MB)
__device__ float g_gx1[BB * TT * G3];  // h0 @ Wih1^T + b_ih1    (~201 MB)
__device__ float g_hlast[BB * HH];     // layer-1 final hidden

// ---------------------------------------------------------------------------
// f32x2 packed helpers
// ---------------------------------------------------------------------------
__device__ __forceinline__ u64 ffma2(u64 a, u64 b, u64 c) {
    u64 d;
    asm("fma.rn.f32x2 %0, %1, %2, %3;" : "=l"(d) : "l"(a), "l"(b), "l"(c));
    return d;
}
__device__ __forceinline__ u64 fadd2(u64 a, u64 b) {
    u64 d;
    asm("add.rn.f32x2 %0, %1, %2;" : "=l"(d) : "l"(a), "l"(b));
    return d;
}
__device__ __forceinline__ float2 unpk(u64 v) {
    float2 r;
    asm("mov.b64 {%0, %1}, %2;" : "=f"(r.x), "=f"(r.y) : "l"(v));
    return r;
}

// single-MUFU activations
__device__ __forceinline__ float mtanh(float v) {
    float r;
    asm("tanh.approx.f32 %0, %1;" : "=f"(r) : "f"(v));
    return r;
}
__device__ __forceinline__ float msig(float v) {
    return fmaf(0.5f, mtanh(0.5f * v), 0.5f);
}

// ---------------------------------------------------------------------------
// Persistent GEMM: OUT[m, j] = bias[j] + sum_k A[m,k] * W[j,k]
// (unchanged from R3 — near crossbar/fma balance)
// ---------------------------------------------------------------------------
__global__ void __launch_bounds__(G3, 1)
gemm_persist(const float* __restrict__ A_ext, const float* __restrict__ W,
             const float* __restrict__ bias, int M, int mode)
{
    extern __shared__ char smraw[];
    ulonglong2* __restrict__ Wsm = (ulonglong2*)smraw;            // 48 KB
    float*      __restrict__ As  = (float*)(smraw + 8 * G3 * 16); // 16 KB

    const float* __restrict__ A = mode ? g_h0 : A_ext;
    float* __restrict__ OUT     = mode ? g_gx1 : g_G0;

    const int j = threadIdx.x;

    for (int idx = j; idx < G3 * 8; idx += G3) {
        int jj = idx >> 3, q = idx & 7;
        Wsm[q * G3 + jj] = ((const ulonglong2*)(W + jj * HH + 96))[q];
    }
    u64 wreg[48];
    {
        const ulonglong2* __restrict__ Wr = (const ulonglong2*)(W + j * HH);
#pragma unroll
        for (int q = 0; q < 24; q++) {
            ulonglong2 w = Wr[q];
            wreg[2 * q] = w.x; wreg[2 * q + 1] = w.y;
        }
    }
    const float bj = bias[j];

    const int ntiles = (M + GM - 1) / GM;
    int it = blockIdx.x;
    if (it >= ntiles) return;

    float4 r0 = make_float4(0, 0, 0, 0), r1 = make_float4(0, 0, 0, 0);
    {
        int m = j >> 5, c = j & 31, mm = it * GM + m;
        if (mm < M) r0 = ((const float4*)(A + mm * HH))[c];
        if (j < 128) {
            int m2 = (j + G3) >> 5, c2 = (j + G3) & 31, mm2 = it * GM + m2;
            if (mm2 < M) r1 = ((const float4*)(A + mm2 * HH))[c2];
        }
    }
    ((float4*)As)[j] = r0;
    if (j < 128) ((float4*)As)[j + G3] = r1;
    __syncthreads();

    int buf = 0;
    for (; it < ntiles; it += NCTA, buf ^= 1) {
        const int nxt = it + NCTA;
        if (nxt < ntiles) {
            r0 = make_float4(0, 0, 0, 0); r1 = make_float4(0, 0, 0, 0);
            int m = j >> 5, c = j & 31, mm = nxt * GM + m;
            if (mm < M) r0 = ((const float4*)(A + mm * HH))[c];
            if (j < 128) {
                int m2 = (j + G3) >> 5, c2 = (j + G3) & 31, mm2 = nxt * GM + m2;
                if (mm2 < M) r1 = ((const float4*)(A + mm2 * HH))[c2];
            }
        }

        u64 acc[GM];
#pragma unroll
        for (int m = 0; m < GM; m++) acc[m] = 0ull;
        const ulonglong2* __restrict__ At = (const ulonglong2*)(As + (buf ? GM * HH : 0));
#pragma unroll
        for (int q = 0; q < 24; q++) {
            u64 wx = wreg[2 * q], wy = wreg[2 * q + 1];
#pragma unroll
            for (int m = 0; m < GM; m++) {
                ulonglong2 a = At[m * 32 + q];
                acc[m] = ffma2(wx, a.x, acc[m]);
                acc[m] = ffma2(wy, a.y, acc[m]);
            }
        }
#pragma unroll
        for (int q = 0; q < 8; q++) {
            ulonglong2 w = Wsm[q * G3 + j];
#pragma unroll
            for (int m = 0; m < GM; m++) {
                ulonglong2 a = At[m * 32 + 24 + q];
                acc[m] = ffma2(w.x, a.x, acc[m]);
                acc[m] = ffma2(w.y, a.y, acc[m]);
            }
        }

        const int m0 = it * GM;
#pragma unroll
        for (int m = 0; m < GM; m++) {
            if (m0 + m < M) {
                float2 s = unpk(acc[m]);
                OUT[(m0 + m) * G3 + j] = bj + s.x + s.y;
            }
        }

        if (nxt < ntiles) {
            float* Ad = As + (buf ? 0 : GM * HH);
            ((float4*)Ad)[j] = r0;
            if (j < 128) ((float4*)Ad)[j + G3] = r1;
        }
        __syncthreads();
    }
}

// ---------------------------------------------------------------------------
// Persistent GRU scan (R4 structure + split tail).
// 128 CTAs x 384 threads, 2 batch rows per CTA. Thread j: gate row j, both rows.
// Whh row j: k[0,96) in 48 u64 regs, k[96,128) in SMEM.
// Roles: j<128 r-threads (also do row-1 state update), 128..255 z-threads
// (produce z, then idle), 256..383 n-threads (publish gh1, do row-0 update).
// ---------------------------------------------------------------------------
__global__ void __launch_bounds__(G3, 1)
gru_scan(const float* __restrict__ Whh, const float* __restrict__ bhh,
         const int* __restrict__ x, int layer)
{
    extern __shared__ ulonglong2 Wsm2[];            // 8*384 ulonglong2 = 48 KB
    __shared__ __align__(16) float hbuf[2][2][HH];  // [buf][row][k]
    __shared__ float2 rp[HH], zp[HH];
    __shared__ float  ghn1[HH];                     // n-thread's gh1 for r tail
    __shared__ int    xs[2][TT];

    const int j  = threadIdx.x;
    const int b0 = blockIdx.x * 2, b1 = b0 + 1;
    const float* __restrict__ gxT = layer ? g_gx1 : g_G0;

    // --- init ---
    u64 wreg[48];
    {
        const ulonglong2* __restrict__ Wr = (const ulonglong2*)(Whh + j * HH);
#pragma unroll
        for (int q = 0; q < 24; q++) {              // k = 0..95
            ulonglong2 w = Wr[q];
            wreg[2 * q]     = w.x;
            wreg[2 * q + 1] = w.y;
        }
#pragma unroll
        for (int q = 0; q < 8; q++)                 // k = 96..127
            Wsm2[q * G3 + j] = Wr[24 + q];
    }
    for (int i = j; i < 2 * TT; i += G3) {
        int r = i >> 9, t = i & (TT - 1);
        ((int*)xs)[i] = x[(b0 + r) * TT + t];
    }
    if (j < HH) { hbuf[0][0][j] = 0.0f; hbuf[0][1][j] = 0.0f; }
    const float bh = bhh[j];
    __syncthreads();

    // preload gx for t=0 (role-specialized; uniform per warp)
    float gxa = 0.0f, gxb = 0.0f, gxn1 = 0.0f;
    {
        if (layer == 0) {
            gxa = __ldg(&gxT[xs[0][0] * G3 + j]);
            if (j < 2 * HH) gxb = __ldg(&gxT[xs[1][0] * G3 + j]);
            if (j < HH)     gxn1 = __ldg(&gxT[xs[1][0] * G3 + j + 2 * HH]);
        } else {
            gxa = __ldg(&gxT[(b0 * TT) * G3 + j]);
            if (j < 2 * HH) gxb = __ldg(&gxT[(b1 * TT) * G3 + j]);
            if (j < HH)     gxn1 = __ldg(&gxT[(b1 * TT) * G3 + j + 2 * HH]);
        }
    }

    for (int t = 0; t < TT; t++) {
        const int buf = t & 1;

        // prefetch next step's input gates (role-specialized)
        float ngxa = 0.0f, ngxb = 0.0f, ngxn1 = 0.0f;
        if (t + 1 < TT) {
            if (layer == 0) {
                ngxa = __ldg(&gxT[xs[0][t + 1] * G3 + j]);
                if (j < 2 * HH) ngxb = __ldg(&gxT[xs[1][t + 1] * G3 + j]);
                if (j < HH)     ngxn1 = __ldg(&gxT[xs[1][t + 1] * G3 + j + 2 * HH]);
            } else {
                ngxa = __ldg(&gxT[(b0 * TT + t + 1) * G3 + j]);
                if (j < 2 * HH) ngxb = __ldg(&gxT[(b1 * TT + t + 1) * G3 + j]);
                if (j < HH)     ngxn1 = __ldg(&gxT[(b1 * TT + t + 1) * G3 + j + 2 * HH]);
            }
        }

        // gh[j] for both rows: packed k-pair dot product
        u64 a0 = 0ull, a1 = 0ull, a2 = 0ull, a3 = 0ull;
        const ulonglong2* __restrict__ h0p = (const ulonglong2*)hbuf[buf][0];
        const ulonglong2* __restrict__ h1p = (const ulonglong2*)hbuf[buf][1];
#pragma unroll
        for (int q = 0; q < 24; q++) {
            ulonglong2 ha = h0p[q];
            ulonglong2 hb = h1p[q];
            a0 = ffma2(wreg[2 * q],     ha.x, a0);
            a1 = ffma2(wreg[2 * q + 1], ha.y, a1);
            a2 = ffma2(wreg[2 * q],     hb.x, a2);
            a3 = ffma2(wreg[2 * q + 1], hb.y, a3);
        }
#pragma unroll
        for (int q = 0; q < 8; q++) {
            ulonglong2 w  = Wsm2[q * G3 + j];
            ulonglong2 ha = h0p[24 + q];
            ulonglong2 hb = h1p[24 + q];
            a0 = ffma2(w.x, ha.x, a0);
            a1 = ffma2(w.y, ha.y, a1);
            a2 = ffma2(w.x, hb.x, a2);
            a3 = ffma2(w.y, hb.y, a3);
        }
        float2 f0 = unpk(fadd2(a0, a1));
        float2 f1 = unpk(fadd2(a2, a3));
        const float gh0 = bh + (f0.x + f0.y);
        const float gh1 = bh + (f1.x + f1.y);

        // split roles
        if (j < HH) {
            // r-threads: produce r gates; after barrier do ROW-1 update
            float r0 = msig(gxa + gh0);
            float r1 = msig(gxb + gh1);
            rp[j] = make_float2(r0, r1);
            float hold1 = hbuf[buf][1][j];
            asm volatile("bar.sync 1, %0;" :: "n"(G3) : "memory");
            float z1 = zp[j].y;
            float g1 = ghn1[j];
            float n1 = mtanh(gxn1 + r1 * g1);
            float hn1 = n1 + z1 * (hold1 - n1);     // (1-z)*n + z*h
            hbuf[buf ^ 1][1][j] = hn1;
            if (layer == 0) {
                g_h0[(b1 * TT + t) * HH + j] = hn1;
            } else if (t == TT - 1) {
                g_hlast[b1 * HH + j] = hn1;
            }
        } else if (j < 2 * HH) {
            // z-threads: produce z gates, then idle
            zp[j - HH] = make_float2(msig(gxa + gh0), msig(gxb + gh1));
            asm volatile("bar.arrive 1, %0;" :: "n"(G3) : "memory");
        } else {
            // n-threads: publish gh1, after barrier do ROW-0 update
            const int i = j - 2 * HH;
            ghn1[i] = gh1;
            float hold0 = hbuf[buf][0][i];
            asm volatile("bar.sync 1, %0;" :: "n"(G3) : "memory");
            float2 rv = rp[i];
            float z0 = zp[i].x;
            float n0 = mtanh(gxa + rv.x * gh0);
            float hn0 = n0 + z0 * (hold0 - n0);
            hbuf[buf ^ 1][0][i] = hn0;
            if (layer == 0) {
                g_h0[(b0 * TT + t) * HH + i] = hn0;
            } else if (t == TT - 1) {
                g_hlast[b0 * HH + i] = hn0;
            }
        }
        __syncthreads();
        gxa = ngxa;
        gxb = ngxb;
        gxn1 = ngxn1;
    }
}

// ---------------------------------------------------------------------------
__global__ void __launch_bounds__(BB)
fc_kernel(const float* __restrict__ fcw, const float* __restrict__ fcb,
          float* __restrict__ out)
{
    __shared__ float ws[3 * HH];
    int b = threadIdx.x;
    for (int i = b; i < 3 * HH; i += BB) ws[i] = fcw[i];
    __syncthreads();
    float a0 = fcb[0], a1 = fcb[1], a2 = fcb[2];
#pragma unroll 4
    for (int k = 0; k < HH; k++) {
        float h = g_hlast[b * HH + k];
        h = h > 0.0f ? h : 0.0f;
        a0 = fmaf(h, ws[k], a0);
        a1 = fmaf(h, ws[HH + k], a1);
        a2 = fmaf(h, ws[2 * HH + k], a2);
    }
    out[b * 3 + 0] = a0;
    out[b * 3 + 1] = a1;
    out[b * 3 + 2] = a2;
}

// ---------------------------------------------------------------------------
extern "C" void kernel_launch(void* const* d_in, const int* in_sizes, int n_in,
                              void* d_out, int out_size)
{
    const int*   x    = (const int*)  d_in[0];
    const float* emb  = (const float*)d_in[1];
    const float* W_ih = (const float*)d_in[2];   // [2][384][128]
    const float* W_hh = (const float*)d_in[3];   // [2][384][128]
    const float* b_ih = (const float*)d_in[4];   // [2][384]
    const float* b_hh = (const float*)d_in[5];   // [2][384]
    const float* fc_w = (const float*)d_in[6];   // [3][128]
    const float* fc_b = (const float*)d_in[7];   // [3]
    float* out = (float*)d_out;

    const int smem_scan = 8 * G3 * (int)sizeof(ulonglong2);               // 48 KB
    const int smem_gemm = 8 * G3 * 16 + 2 * GM * HH * (int)sizeof(float); // 64 KB
    cudaFuncSetAttribute(gru_scan, cudaFuncAttributeMaxDynamicSharedMemorySize,
                         smem_scan);
    cudaFuncSetAttribute(gemm_persist, cudaFuncAttributeMaxDynamicSharedMemorySize,
                         smem_gemm);

    // 1) G0 = emb @ Wih0^T + b_ih0  (vocab-side precompute: V < B*T)
    gemm_persist<<<NCTA, G3, smem_gemm>>>(emb, W_ih, b_ih, VV, 0);
    // 2) layer-0 scan (gx gathered from G0), writes g_h0
    gru_scan<<<BB / 2, G3, smem_scan>>>(W_hh, b_hh, x, 0);
    // 3) gx1 = h0 @ Wih1^T + b_ih1
    gemm_persist<<<NCTA, G3, smem_gemm>>>(nullptr, W_ih + G3 * HH, b_ih + G3, BB * TT, 1);
    // 4) layer-1 scan, writes g_hlast
    gru_scan<<<BB / 2, G3, smem_scan>>>(W_hh + G3 * HH, b_hh + G3, x, 1);
    // 5) head
    fc_kernel<<<1, BB>>>(fc_w, fc_b, out);
}